// round 5
// baseline (speedup 1.0000x reference)
#include <cuda_runtime.h>

typedef unsigned long long ull;

#define T_ 32
#define H_ 56
#define W_ 56
#define HW 3136
#define C_ 64
#define B_ 4
#define TILEH 8
#define NTILES 7
#define NT 224            // 28 pixel-pairs * 8 rows
#define RS 60             // padded row stride (floats)
#define PR (TILEH + 2)
#define SLOTS 9           // plane ring; 8 collides with next-round staging (race)
#define PLANEF (PR * RS)  // 600

#define MODP(x, m) ((((x) + 72) % (m)))   // +72 divisible by 3,4,6,8,9

#define FMA2(acc, w, x) \
    asm("fma.rn.f32x2 %0, %1, %2, %0;" : "+l"(acc) : "l"(w), "l"(x))
#define UNPK(lo, hi, p) \
    asm("mov.b64 {%0,%1}, %2;" : "=f"(lo), "=f"(hi) : "l"(p))
#define MIDP(m, p01, p23) \
    asm("{ .reg .b32 t0,t1,t2,t3;\n\t mov.b64 {t0,t1}, %1;\n\t" \
        " mov.b64 {t2,t3}, %2;\n\t mov.b64 %0, {t1,t2}; }" \
        : "=l"(m) : "l"(p01), "l"(p23))
#define CPA(saddr, gaddr, sz) \
    asm volatile("cp.async.ca.shared.global [%0], [%1], 4, %2;" \
                 :: "r"(saddr), "l"(gaddr), "r"(sz) : "memory")
#define CP_COMMIT asm volatile("cp.async.commit_group;" ::: "memory")
#define CP_WAIT1  asm volatile("cp.async.wait_group 1;" ::: "memory")

__device__ __forceinline__ float sgm(float v) {
    return __fdividef(1.0f, 1.0f + __expf(-v)) - 0.5f;
}

__global__ void __launch_bounds__(NT, 3) tts_kernel(
    const float* __restrict__ xg,
    const float* __restrict__ w1g, const float* __restrict__ b1g,
    const float* __restrict__ w2g, const float* __restrict__ b2g,
    const float* __restrict__ w3g, const float* __restrict__ b3g,
    const float* __restrict__ wgg,
    float* __restrict__ outg)
{
    __shared__ __align__(16) float plane[SLOTS][PR][RS];     // 21600 B
    __shared__ __align__(16) ull wdup[9][3][4];              // dup'd weights
    __shared__ __align__(16) float2 hsm[5][NT];              // h2 (2) + h3 (3)

    const int tid  = threadIdx.x;
    const int bx   = blockIdx.x;
    const int tile = bx % NTILES;
    const int bc   = bx / NTILES;
    const int c    = bc % C_;
    const int h0   = tile * TILEH;

    const float* __restrict__ xin = xg + (size_t)bc * (T_ * HW);
    float* __restrict__ op = outg + (size_t)bc * (T_ * HW);

    // Stage duplicated weights: wdup[sl][dy][j] = (w,w) for tap dy*3+j
    if (tid < 108) {
        int j = tid & 3, rowi = tid >> 2;       // 27 rows
        int sl = rowi / 3, dy = rowi % 3;
        int i = sl / 3, s = sl % 3;
        ull v = 0;
        if (j < 3) {
            const float* wp = (i == 0) ? w1g : (i == 1) ? w2g : w3g;
            unsigned b = __float_as_uint(wp[c * 27 + s * 9 + dy * 3 + j]);
            v = ((ull)b << 32) | b;
        }
        wdup[sl][dy][j] = v;
    }

    const float bias0 = b1g[c], bias1 = b2g[c], bias2 = b3g[c];
    const float wt0 = wgg[0], wt1 = wgg[1], wt2 = wgg[2];

    // Staging geometry: 600 floats/plane, 3 elems/thread (k=2 partial)
    unsigned sb[3]; const char* gb[3]; int sz[3];
    #pragma unroll
    for (int k = 0; k < 3; ++k) {
        int idx = tid + k * NT;
        bool a = (idx < PLANEF);
        int r = idx / RS, col = idx % RS;
        int y = h0 - 1 + r, xw = col - 1;
        bool in = a && (y >= 0) && (y < H_) && (xw >= 0) && (xw < W_);
        sb[k] = (unsigned)((r * RS + col) * 4);
        gb[k] = (const char*)(xin + (in ? (y * W_ + xw) : 0));
        sz[k] = in ? 4 : 0;
    }
    const bool act2 = (tid + 2 * NT) < PLANEF;
    const unsigned pbase = (unsigned)__cvta_generic_to_shared(&plane[0][0][0]);
    const float* const plane0 = &plane[0][0][0];

    auto stage = [&](int p) {   // p is a compile-time literal after unroll
        unsigned sdst = pbase + (unsigned)(MODP(p, SLOTS) * PLANEF * 4);
        size_t go = (size_t)p * (HW * 4);
        CPA(sdst + sb[0], gb[0] + go, sz[0]);
        CPA(sdst + sb[1], gb[1] + go, sz[1]);
        if (act2) CPA(sdst + sb[2], gb[2] + go, sz[2]);
    };

    // Zero histories (same-thread access only)
    #pragma unroll
    for (int j = 0; j < 5; ++j) hsm[j][tid] = make_float2(0.f, 0.f);

    const int row   = tid / 28;
    const int w0    = (tid % 28) * 2;
    const int nb0   = row * RS + w0;
    const int obase = (h0 + row) * W_ + w0;

    // Accumulator rings (packed f32x2), gate ring, conv1 history in regs
    ull R1[4], R2[6], R3[8];
    float Gx[3], Gy[3];
    float2 h1 = make_float2(0.f, 0.f);
    #pragma unroll
    for (int j = 0; j < 4; ++j) R1[j] = 0ull;
    #pragma unroll
    for (int j = 0; j < 6; ++j) R2[j] = 0ull;
    #pragma unroll
    for (int j = 0; j < 8; ++j) R3[j] = 0ull;
    #pragma unroll
    for (int j = 0; j < 3; ++j) { Gx[j] = 0.f; Gy[j] = 0.f; }

    // ring target for slice sl applied at plane tau: t = tau + (1-s)*d
    auto aref = [&](int sl, int t) -> ull& {
        int cv = sl / 3, s = sl % 3;
        if (cv == 0) return R1[MODP(t + (1 - s) * 1, 4)];
        if (cv == 1) return R2[MODP(t + (1 - s) * 2, 6)];
        return R3[MODP(t + (1 - s) * 3, 8)];
    };

    auto completion = [&](int tau) {
        // conv1: y1(tau-1)
        if (tau >= 1 && tau <= T_) {
            float lo, hi; UNPK(lo, hi, R1[MODP(tau - 1, 4)]);
            float y0 = lo + bias0, y1 = hi + bias0;
            float d0 = y0, d1 = y1;
            if (tau >= 2) { d0 -= h1.x; d1 -= h1.y; }
            h1 = make_float2(y0, y1);
            int gs = MODP(tau - 1, 3);
            Gx[gs] += sgm(d0) * wt0;
            Gy[gs] += sgm(d1) * wt0;
        }
        if (tau <= T_) R1[MODP(tau - 1, 4)] = 0ull;

        // conv2: y2(tau-2)
        if (tau >= 2 && tau <= T_ + 1) {
            float lo, hi; UNPK(lo, hi, R2[MODP(tau - 2, 6)]);
            float y0 = lo + bias1, y1 = hi + bias1;
            float d0 = y0, d1 = y1;
            const int hs = tau % 2;             // (tau-2)%2
            if (tau >= 4) {
                float2 h = hsm[hs][tid];
                d0 -= h.x; d1 -= h.y;
            }
            hsm[hs][tid] = make_float2(y0, y1);
            int gs = MODP(tau - 2, 3);
            Gx[gs] += sgm(d0) * wt1;
            Gy[gs] += sgm(d1) * wt1;
        }
        if (tau <= T_ + 1) R2[MODP(tau - 2, 6)] = 0ull;

        // conv3: y3(tau-3) -> gate complete -> output t = tau-3
        if (tau >= 3 && tau <= T_ + 2) {
            float lo, hi; UNPK(lo, hi, R3[MODP(tau - 3, 8)]);
            float y0 = lo + bias2, y1 = hi + bias2;
            float d0 = y0, d1 = y1;
            const int hs = 2 + tau % 3;         // (tau-3)%3
            if (tau >= 6) {
                float2 h = hsm[hs][tid];
                d0 -= h.x; d1 -= h.y;
            }
            hsm[hs][tid] = make_float2(y0, y1);
            int gs = MODP(tau - 3, 3);
            float g0 = Gx[gs] + sgm(d0) * wt2;
            float g1 = Gy[gs] + sgm(d1) * wt2;
            Gx[gs] = 0.f; Gy[gs] = 0.f;

            const int tout = tau - 3;
            const float* pc = plane0 + MODP(tau - 3, SLOTS) * PLANEF;
            float cx0 = pc[nb0 + RS + 1];
            float cx1 = pc[nb0 + RS + 2];
            float2 o = make_float2(cx0 * g0, cx1 * g1);
            *(float2*)(op + (size_t)tout * HW + obase) = o;
        }
        if (tau <= T_ + 2) R3[MODP(tau - 3, 8)] = 0ull;
    };

    // Prologue: stage planes 0,1 as one cp.async group
    stage(0); stage(1); CP_COMMIT;

    #pragma unroll
    for (int pp = 0; pp < 18; ++pp) {
        const int tA = 2 * pp, tB = 2 * pp + 1;

        if (tA < T_) {
            // Stage planes tA+2, tB+2 (overlaps with this round's compute)
            if (tA + 2 < T_) stage(tA + 2);
            if (tB + 2 < T_) stage(tB + 2);
            CP_COMMIT;            // always commit (possibly empty group)
            CP_WAIT1;             // planes tA,tB (previous group) resident
            __syncthreads();

            // Fused pair conv: weights loaded once, applied to both planes
            const float* plA = plane0 + MODP(tA, SLOTS) * PLANEF;
            const float* plB = plane0 + MODP(tB, SLOTS) * PLANEF;
            #pragma unroll
            for (int dy = 0; dy < 3; ++dy) {
                const float* ra = plA + nb0 + dy * RS;
                const float* rb = plB + nb0 + dy * RS;
                ull a01 = *(const ull*)(ra);
                ull a23 = *(const ull*)(ra + 2);
                ull b01 = *(const ull*)(rb);
                ull b23 = *(const ull*)(rb + 2);
                ull am, bm;
                MIDP(am, a01, a23);
                MIDP(bm, b01, b23);
                #pragma unroll
                for (int sl = 0; sl < 9; ++sl) {
                    const ulonglong2 wv = *(const ulonglong2*)(&wdup[sl][dy][0]);
                    const ull w2v = wdup[sl][dy][2];
                    ull& qa = aref(sl, tA);
                    FMA2(qa, wv.x, a01); FMA2(qa, wv.y, am); FMA2(qa, w2v, a23);
                    ull& qb = aref(sl, tB);
                    FMA2(qb, wv.x, b01); FMA2(qb, wv.y, bm); FMA2(qb, w2v, b23);
                }
            }
        }

        completion(tA);
        if (tB < T_ + 3) completion(tB);
    }
}

extern "C" void kernel_launch(void* const* d_in, const int* in_sizes, int n_in,
                              void* d_out, int out_size) {
    const float* x  = (const float*)d_in[0];
    const float* w1 = (const float*)d_in[1];
    const float* b1 = (const float*)d_in[2];
    const float* w2 = (const float*)d_in[3];
    const float* b2 = (const float*)d_in[4];
    const float* w3 = (const float*)d_in[5];
    const float* b3 = (const float*)d_in[6];
    const float* wg = (const float*)d_in[7];
    float* out = (float*)d_out;

    dim3 grid(B_ * C_ * NTILES);   // 1792
    dim3 block(NT);                // 224
    tts_kernel<<<grid, block>>>(x, w1, b1, w2, b2, w3, b3, wg, out);
}

// round 6
// speedup vs baseline: 1.0234x; 1.0234x over previous
#include <cuda_runtime.h>

typedef unsigned long long ull;

#define T_ 32
#define H_ 56
#define W_ 56
#define HW 3136
#define C_ 64
#define B_ 4
#define TILEH 8
#define NTILES 7
#define NT 224            // 28 pixel-pairs * 8 rows
#define RS 60             // padded row stride (floats)
#define PR (TILEH + 2)
#define SLOTS 9           // plane ring; 8 collides with next-round staging
#define PLANEF (PR * RS)  // 600

#define MODP(x, m) ((((x) + 72) % (m)))   // +72 divisible by 3,4,6,8,9

#define FMA2(acc, w, x) \
    asm("fma.rn.f32x2 %0, %1, %2, %0;" : "+l"(acc) : "l"(w), "l"(x))
#define UNPK(lo, hi, p) \
    asm("mov.b64 {%0,%1}, %2;" : "=f"(lo), "=f"(hi) : "l"(p))
#define MIDP(m, p01, p23) \
    asm("{ .reg .b32 t0,t1,t2,t3;\n\t mov.b64 {t0,t1}, %1;\n\t" \
        " mov.b64 {t2,t3}, %2;\n\t mov.b64 %0, {t1,t2}; }" \
        : "=l"(m) : "l"(p01), "l"(p23))
#define CPA(saddr, gaddr, sz) \
    asm volatile("cp.async.ca.shared.global [%0], [%1], 4, %2;" \
                 :: "r"(saddr), "l"(gaddr), "r"(sz) : "memory")
#define CP_COMMIT asm volatile("cp.async.commit_group;" ::: "memory")
#define CP_WAIT1  asm volatile("cp.async.wait_group 1;" ::: "memory")

__device__ __forceinline__ float sgm(float v) {
    return __fdividef(1.0f, 1.0f + __expf(-v)) - 0.5f;
}

__global__ void __launch_bounds__(NT, 4) tts_kernel(
    const float* __restrict__ xg,
    const float* __restrict__ w1g, const float* __restrict__ b1g,
    const float* __restrict__ w2g, const float* __restrict__ b2g,
    const float* __restrict__ w3g, const float* __restrict__ b3g,
    const float* __restrict__ wgg,
    float* __restrict__ outg)
{
    __shared__ __align__(16) float plane[SLOTS][PR][RS];     // 21600 B
    __shared__ __align__(16) ull wdup[9][3][4];              // dup'd weights
    __shared__ __align__(16) float2 hsm[6][NT];              // 0=h1,1..2=h2,3..5=h3
    __shared__ __align__(16) float2 gbuf[3][NT];             // gate ring in smem

    const int tid  = threadIdx.x;
    const int bx   = blockIdx.x;
    const int tile = bx % NTILES;
    const int bc   = bx / NTILES;
    const int c    = bc % C_;
    const int h0   = tile * TILEH;

    const float* __restrict__ xin = xg + (size_t)bc * (T_ * HW);
    float* __restrict__ op = outg + (size_t)bc * (T_ * HW);

    // Stage duplicated weights: wdup[sl][dy][j] = (w,w) for tap dy*3+j
    if (tid < 108) {
        int j = tid & 3, rowi = tid >> 2;       // 27 rows
        int sl = rowi / 3, dy = rowi % 3;
        int i = sl / 3, s = sl % 3;
        ull v = 0;
        if (j < 3) {
            const float* wp = (i == 0) ? w1g : (i == 1) ? w2g : w3g;
            unsigned b = __float_as_uint(wp[c * 27 + s * 9 + dy * 3 + j]);
            v = ((ull)b << 32) | b;
        }
        wdup[sl][dy][j] = v;
    }

    const float bias0 = b1g[c], bias1 = b2g[c], bias2 = b3g[c];
    const float wt0 = wgg[0], wt1 = wgg[1], wt2 = wgg[2];

    // Staging geometry: 600 floats/plane, 3 elems/thread (k=2 partial)
    unsigned sb[3]; const char* gb[3]; int sz[3];
    #pragma unroll
    for (int k = 0; k < 3; ++k) {
        int idx = tid + k * NT;
        bool a = (idx < PLANEF);
        int r = idx / RS, col = idx % RS;
        int y = h0 - 1 + r, xw = col - 1;
        bool in = a && (y >= 0) && (y < H_) && (xw >= 0) && (xw < W_);
        sb[k] = (unsigned)((r * RS + col) * 4);
        gb[k] = (const char*)(xin + (in ? (y * W_ + xw) : 0));
        sz[k] = in ? 4 : 0;
    }
    const bool act2 = (tid + 2 * NT) < PLANEF;
    const unsigned pbase = (unsigned)__cvta_generic_to_shared(&plane[0][0][0]);
    const float* const plane0 = &plane[0][0][0];

    auto stage = [&](int p) {   // p is a compile-time literal after unroll
        unsigned sdst = pbase + (unsigned)(MODP(p, SLOTS) * PLANEF * 4);
        size_t go = (size_t)p * (HW * 4);
        CPA(sdst + sb[0], gb[0] + go, sz[0]);
        CPA(sdst + sb[1], gb[1] + go, sz[1]);
        if (act2) CPA(sdst + sb[2], gb[2] + go, sz[2]);
    };

    // Zero histories + gate ring (same-thread access only)
    #pragma unroll
    for (int j = 0; j < 6; ++j) hsm[j][tid] = make_float2(0.f, 0.f);
    #pragma unroll
    for (int j = 0; j < 3; ++j) gbuf[j][tid] = make_float2(0.f, 0.f);

    const int row   = tid / 28;
    const int w0    = (tid % 28) * 2;
    const int nb0   = row * RS + w0;
    const int obase = (h0 + row) * W_ + w0;

    // Accumulator rings (packed f32x2)
    ull R1[4], R2[6], R3[8];
    #pragma unroll
    for (int j = 0; j < 4; ++j) R1[j] = 0ull;
    #pragma unroll
    for (int j = 0; j < 6; ++j) R2[j] = 0ull;
    #pragma unroll
    for (int j = 0; j < 8; ++j) R3[j] = 0ull;

    // ring target for slice sl applied at plane tau: t = tau + (1-s)*d
    auto aref = [&](int sl, int t) -> ull& {
        int cv = sl / 3, s = sl % 3;
        if (cv == 0) return R1[MODP(t + (1 - s) * 1, 4)];
        if (cv == 1) return R2[MODP(t + (1 - s) * 2, 6)];
        return R3[MODP(t + (1 - s) * 3, 8)];
    };

    auto completion = [&](int tau) {
        // conv1: y1(tau-1)
        if (tau >= 1 && tau <= T_) {
            float lo, hi; UNPK(lo, hi, R1[MODP(tau - 1, 4)]);
            float y0 = lo + bias0, y1 = hi + bias0;
            float d0 = y0, d1 = y1;
            if (tau >= 2) {
                float2 h = hsm[0][tid];
                d0 -= h.x; d1 -= h.y;
            }
            hsm[0][tid] = make_float2(y0, y1);
            float2 g = gbuf[MODP(tau - 1, 3)][tid];
            g.x += sgm(d0) * wt0;
            g.y += sgm(d1) * wt0;
            gbuf[MODP(tau - 1, 3)][tid] = g;
        }
        if (tau <= T_) R1[MODP(tau - 1, 4)] = 0ull;

        // conv2: y2(tau-2)
        if (tau >= 2 && tau <= T_ + 1) {
            float lo, hi; UNPK(lo, hi, R2[MODP(tau - 2, 6)]);
            float y0 = lo + bias1, y1 = hi + bias1;
            float d0 = y0, d1 = y1;
            const int hs = 1 + (tau % 2);       // (tau-2)%2
            if (tau >= 4) {
                float2 h = hsm[hs][tid];
                d0 -= h.x; d1 -= h.y;
            }
            hsm[hs][tid] = make_float2(y0, y1);
            float2 g = gbuf[MODP(tau - 2, 3)][tid];
            g.x += sgm(d0) * wt1;
            g.y += sgm(d1) * wt1;
            gbuf[MODP(tau - 2, 3)][tid] = g;
        }
        if (tau <= T_ + 1) R2[MODP(tau - 2, 6)] = 0ull;

        // conv3: y3(tau-3) -> gate complete -> output t = tau-3
        if (tau >= 3 && tau <= T_ + 2) {
            float lo, hi; UNPK(lo, hi, R3[MODP(tau - 3, 8)]);
            float y0 = lo + bias2, y1 = hi + bias2;
            float d0 = y0, d1 = y1;
            const int hs = 3 + (tau % 3);       // (tau-3)%3
            if (tau >= 6) {
                float2 h = hsm[hs][tid];
                d0 -= h.x; d1 -= h.y;
            }
            hsm[hs][tid] = make_float2(y0, y1);
            float2 g = gbuf[MODP(tau - 3, 3)][tid];
            float g0 = g.x + sgm(d0) * wt2;
            float g1 = g.y + sgm(d1) * wt2;
            gbuf[MODP(tau - 3, 3)][tid] = make_float2(0.f, 0.f);

            const int tout = tau - 3;
            const float* pc = plane0 + MODP(tau - 3, SLOTS) * PLANEF;
            float cx0 = pc[nb0 + RS + 1];
            float cx1 = pc[nb0 + RS + 2];
            float2 o = make_float2(cx0 * g0, cx1 * g1);
            *(float2*)(op + (size_t)tout * HW + obase) = o;
        }
        if (tau <= T_ + 2) R3[MODP(tau - 3, 8)] = 0ull;
    };

    // Prologue: stage planes 0,1 as one cp.async group
    stage(0); stage(1); CP_COMMIT;

    #pragma unroll
    for (int pp = 0; pp < 18; ++pp) {
        const int tA = 2 * pp, tB = 2 * pp + 1;

        if (tA < T_) {
            // Stage planes tA+2, tB+2 (overlaps with this round's compute)
            if (tA + 2 < T_) stage(tA + 2);
            if (tB + 2 < T_) stage(tB + 2);
            CP_COMMIT;            // always commit (possibly empty group)
            CP_WAIT1;             // planes tA,tB (previous group) resident
            __syncthreads();

            // Fused pair conv: weights loaded once, applied to both planes
            const float* plA = plane0 + MODP(tA, SLOTS) * PLANEF;
            const float* plB = plane0 + MODP(tB, SLOTS) * PLANEF;
            #pragma unroll
            for (int dy = 0; dy < 3; ++dy) {
                const float* ra = plA + nb0 + dy * RS;
                const float* rb = plB + nb0 + dy * RS;
                ull a01 = *(const ull*)(ra);
                ull a23 = *(const ull*)(ra + 2);
                ull b01 = *(const ull*)(rb);
                ull b23 = *(const ull*)(rb + 2);
                ull am, bm;
                MIDP(am, a01, a23);
                MIDP(bm, b01, b23);
                #pragma unroll
                for (int sl = 0; sl < 9; ++sl) {
                    const ulonglong2 wv = *(const ulonglong2*)(&wdup[sl][dy][0]);
                    const ull w2v = wdup[sl][dy][2];
                    ull& qa = aref(sl, tA);
                    FMA2(qa, wv.x, a01); FMA2(qa, wv.y, am); FMA2(qa, w2v, a23);
                    ull& qb = aref(sl, tB);
                    FMA2(qb, wv.x, b01); FMA2(qb, wv.y, bm); FMA2(qb, w2v, b23);
                }
            }
        }

        completion(tA);
        if (tB < T_ + 3) completion(tB);
    }
}

extern "C" void kernel_launch(void* const* d_in, const int* in_sizes, int n_in,
                              void* d_out, int out_size) {
    const float* x  = (const float*)d_in[0];
    const float* w1 = (const float*)d_in[1];
    const float* b1 = (const float*)d_in[2];
    const float* w2 = (const float*)d_in[3];
    const float* b2 = (const float*)d_in[4];
    const float* w3 = (const float*)d_in[5];
    const float* b3 = (const float*)d_in[6];
    const float* wg = (const float*)d_in[7];
    float* out = (float*)d_out;

    // ~37.7 KB static smem/CTA; ask for max shared carveout so 4 CTAs/SM
    // (151 KB) aren't capped by a conservative default split. Deterministic,
    // host-side, not a stream op (executes outside graph capture).
    static int carveout_set = 0;
    if (!carveout_set) {
        cudaFuncSetAttribute(tts_kernel,
                             cudaFuncAttributePreferredSharedMemoryCarveout,
                             100);
        carveout_set = 1;
    }

    dim3 grid(B_ * C_ * NTILES);   // 1792
    dim3 block(NT);                // 224
    tts_kernel<<<grid, block>>>(x, w1, b1, w2, b2, w3, b3, wg, out);
}

// round 8
// speedup vs baseline: 1.0247x; 1.0013x over previous
#include <cuda_runtime.h>

typedef unsigned long long ull;

#define T_ 32
#define H_ 56
#define W_ 56
#define HW 3136
#define C_ 64
#define B_ 4
#define TILEH 8
#define NTILES 7
#define NT 224            // 28 pixel-pairs * 8 rows
#define RS 60             // padded row stride (floats)
#define PR (TILEH + 2)
#define SLOTS 12          // stage{+3..+5} vs reads{-6..+2}: diffs 1..11, all !=0 mod 12
#define PLANEF (PR * RS)  // 600

#define MODP(x, m) ((((x) + 1260) % (m)))   // 1260 divisible by 3,5,7,9,12

#define FMA2(acc, w, x) \
    asm("fma.rn.f32x2 %0, %1, %2, %0;" : "+l"(acc) : "l"(w), "l"(x))
#define MUL2(acc, w, x) \
    asm("mul.rn.f32x2 %0, %1, %2;" : "=l"(acc) : "l"(w), "l"(x))
#define UNPK(lo, hi, p) \
    asm("mov.b64 {%0,%1}, %2;" : "=f"(lo), "=f"(hi) : "l"(p))
#define MIDP(m, p01, p23) \
    asm("{ .reg .b32 t0,t1,t2,t3;\n\t mov.b64 {t0,t1}, %1;\n\t" \
        " mov.b64 {t2,t3}, %2;\n\t mov.b64 %0, {t1,t2}; }" \
        : "=l"(m) : "l"(p01), "l"(p23))
#define CPA(saddr, gaddr, sz) \
    asm volatile("cp.async.ca.shared.global [%0], [%1], 4, %2;" \
                 :: "r"(saddr), "l"(gaddr), "r"(sz) : "memory")
#define CP_COMMIT asm volatile("cp.async.commit_group;" ::: "memory")
#define CP_WAIT1  asm volatile("cp.async.wait_group 1;" ::: "memory")

__device__ __forceinline__ float sgm(float v) {
    return __fdividef(1.0f, 1.0f + __expf(-v)) - 0.5f;
}

__global__ void __launch_bounds__(NT, 3) tts_kernel(
    const float* __restrict__ xg,
    const float* __restrict__ w1g, const float* __restrict__ b1g,
    const float* __restrict__ w2g, const float* __restrict__ b2g,
    const float* __restrict__ w3g, const float* __restrict__ b3g,
    const float* __restrict__ wgg,
    float* __restrict__ outg)
{
    __shared__ __align__(16) float plane[SLOTS][PR][RS];     // 28800 B
    __shared__ __align__(16) ull wdup[9][3][4];              // dup'd weights
    __shared__ __align__(16) float2 hsm[6][NT];              // 0=h1,1..2=h2,3..5=h3
    __shared__ __align__(16) float2 gbuf[3][NT];             // gate ring

    const int tid  = threadIdx.x;
    const int bx   = blockIdx.x;
    const int tile = bx % NTILES;
    const int bc   = bx / NTILES;
    const int c    = bc % C_;
    const int h0   = tile * TILEH;

    const float* __restrict__ xin = xg + (size_t)bc * (T_ * HW);
    float* __restrict__ op = outg + (size_t)bc * (T_ * HW);

    // Stage duplicated weights: wdup[sl][dy][j] = (w,w) for tap dy*3+j
    if (tid < 108) {
        int j = tid & 3, rowi = tid >> 2;
        int sl = rowi / 3, dy = rowi % 3;
        int i = sl / 3, s = sl % 3;
        ull v = 0;
        if (j < 3) {
            const float* wp = (i == 0) ? w1g : (i == 1) ? w2g : w3g;
            unsigned b = __float_as_uint(wp[c * 27 + s * 9 + dy * 3 + j]);
            v = ((ull)b << 32) | b;
        }
        wdup[sl][dy][j] = v;
    }

    const float bias0 = b1g[c], bias1 = b2g[c], bias2 = b3g[c];
    const float wt0 = wgg[0], wt1 = wgg[1], wt2 = wgg[2];

    // Staging geometry: 600 floats/plane, 3 elems/thread (k=2 partial)
    unsigned sb[3]; const char* gb[3]; int sz[3];
    #pragma unroll
    for (int k = 0; k < 3; ++k) {
        int idx = tid + k * NT;
        bool a = (idx < PLANEF);
        int r = idx / RS, col = idx % RS;
        int y = h0 - 1 + r, xw = col - 1;
        bool in = a && (y >= 0) && (y < H_) && (xw >= 0) && (xw < W_);
        sb[k] = (unsigned)((r * RS + col) * 4);
        gb[k] = (const char*)(xin + (in ? (y * W_ + xw) : 0));
        sz[k] = in ? 4 : 0;
    }
    const bool act2 = (tid + 2 * NT) < PLANEF;
    const unsigned pbase = (unsigned)__cvta_generic_to_shared(&plane[0][0][0]);
    const float* const plane0 = &plane[0][0][0];

    auto stage = [&](int p) {   // p compile-time literal after unroll
        unsigned sdst = pbase + (unsigned)(MODP(p, SLOTS) * PLANEF * 4);
        size_t go = (size_t)p * (HW * 4);
        CPA(sdst + sb[0], gb[0] + go, sz[0]);
        CPA(sdst + sb[1], gb[1] + go, sz[1]);
        if (act2) CPA(sdst + sb[2], gb[2] + go, sz[2]);
    };

    // Zero histories + gate ring (same-thread access only)
    #pragma unroll
    for (int j = 0; j < 6; ++j) hsm[j][tid] = make_float2(0.f, 0.f);
    #pragma unroll
    for (int j = 0; j < 3; ++j) gbuf[j][tid] = make_float2(0.f, 0.f);

    const int row   = tid / 28;
    const int w0    = (tid % 28) * 2;
    const int nb0   = row * RS + w0;
    const int obase = (h0 + row) * W_ + w0;

    // Accumulator rings (packed f32x2). Zero-init needed only for targets
    // t < d (which never receive an s=0 overwrite); all other slot uses
    // begin with MUL2 from slice s=0, so no per-round resets exist.
    ull R1[5], R2[7], R3[9];
    #pragma unroll
    for (int j = 0; j < 5; ++j) R1[j] = 0ull;
    #pragma unroll
    for (int j = 0; j < 7; ++j) R2[j] = 0ull;
    #pragma unroll
    for (int j = 0; j < 9; ++j) R3[j] = 0ull;

    // ring target for slice sl applied at plane p: t = p + (1-s)*d
    auto aref = [&](int sl, int t) -> ull& {
        int cv = sl / 3, s = sl % 3;
        if (cv == 0) return R1[MODP(t + (1 - s) * 1, 5)];
        if (cv == 1) return R2[MODP(t + (1 - s) * 2, 7)];
        return R3[MODP(t + (1 - s) * 3, 9)];
    };

    auto completion = [&](int tau) {
        // conv1: y1(tau-1). First gate writer -> overwrite gbuf (STS only).
        if (tau >= 1 && tau <= T_) {
            float lo, hi; UNPK(lo, hi, R1[MODP(tau - 1, 5)]);
            float y0 = lo + bias0, y1 = hi + bias0;
            float d0 = y0, d1 = y1;
            if (tau >= 2) {
                float2 h = hsm[0][tid];
                d0 -= h.x; d1 -= h.y;
            }
            hsm[0][tid] = make_float2(y0, y1);
            gbuf[MODP(tau - 1, 3)][tid] =
                make_float2(sgm(d0) * wt0, sgm(d1) * wt0);
        }

        // conv2: y2(tau-2), gate RMW
        if (tau >= 2 && tau <= T_ + 1) {
            float lo, hi; UNPK(lo, hi, R2[MODP(tau - 2, 7)]);
            float y0 = lo + bias1, y1 = hi + bias1;
            float d0 = y0, d1 = y1;
            const int hs = 1 + (tau % 2);       // (tau-2)%2
            if (tau >= 4) {
                float2 h = hsm[hs][tid];
                d0 -= h.x; d1 -= h.y;
            }
            hsm[hs][tid] = make_float2(y0, y1);
            float2 g = gbuf[MODP(tau - 2, 3)][tid];
            g.x += sgm(d0) * wt1;
            g.y += sgm(d1) * wt1;
            gbuf[MODP(tau - 2, 3)][tid] = g;
        }

        // conv3: y3(tau-3) -> gate complete -> output t = tau-3 (no reset STS)
        if (tau >= 3 && tau <= T_ + 2) {
            float lo, hi; UNPK(lo, hi, R3[MODP(tau - 3, 9)]);
            float y0 = lo + bias2, y1 = hi + bias2;
            float d0 = y0, d1 = y1;
            const int hs = 3 + (tau % 3);       // (tau-3)%3
            if (tau >= 6) {
                float2 h = hsm[hs][tid];
                d0 -= h.x; d1 -= h.y;
            }
            hsm[hs][tid] = make_float2(y0, y1);
            float2 g = gbuf[MODP(tau - 3, 3)][tid];
            float g0 = g.x + sgm(d0) * wt2;
            float g1 = g.y + sgm(d1) * wt2;

            const int tout = tau - 3;
            const float* pc = plane0 + MODP(tau - 3, SLOTS) * PLANEF;
            float cx0 = pc[nb0 + RS + 1];
            float cx1 = pc[nb0 + RS + 2];
            float2 o = make_float2(cx0 * g0, cx1 * g1);
            *(float2*)(op + (size_t)tout * HW + obase) = o;
        }
    };

    // Prologue: stage planes 0,1,2 as one cp.async group
    stage(0); stage(1); stage(2); CP_COMMIT;

    #pragma unroll
    for (int q = 0; q < 12; ++q) {
        const int tA = 3 * q;

        if (tA < T_) {
            // Stage next triple (overlaps with this round's compute)
            #pragma unroll
            for (int j = 0; j < 3; ++j)
                if (tA + 3 + j < T_) stage(tA + 3 + j);
            CP_COMMIT;            // always commit (possibly empty group)
            CP_WAIT1;             // previous triple resident
            __syncthreads();

            // Fused triple conv: each weight load feeds up to 3 planes
            #pragma unroll
            for (int dy = 0; dy < 3; ++dy) {
                ull a01[3], a23[3], am[3];
                #pragma unroll
                for (int j = 0; j < 3; ++j) {
                    if (tA + j < T_) {
                        const float* rp = plane0
                            + MODP(tA + j, SLOTS) * PLANEF + nb0 + dy * RS;
                        a01[j] = *(const ull*)(rp);
                        a23[j] = *(const ull*)(rp + 2);
                        MIDP(am[j], a01[j], a23[j]);
                    }
                }
                #pragma unroll
                for (int sl = 0; sl < 9; ++sl) {
                    const ulonglong2 wv = *(const ulonglong2*)(&wdup[sl][dy][0]);
                    const ull w2v = wdup[sl][dy][2];
                    #pragma unroll
                    for (int j = 0; j < 3; ++j) {
                        if (tA + j < T_) {
                            ull& q_ = aref(sl, tA + j);
                            if ((sl % 3) == 0 && dy == 0) {
                                // slice s=0, first tap: fresh overwrite
                                MUL2(q_, wv.x, a01[j]);
                                FMA2(q_, wv.y, am[j]);
                                FMA2(q_, w2v, a23[j]);
                            } else {
                                FMA2(q_, wv.x, a01[j]);
                                FMA2(q_, wv.y, am[j]);
                                FMA2(q_, w2v, a23[j]);
                            }
                        }
                    }
                }
            }
        }

        #pragma unroll
        for (int j = 0; j < 3; ++j)
            if (tA + j <= T_ + 2) completion(tA + j);
    }
}

extern "C" void kernel_launch(void* const* d_in, const int* in_sizes, int n_in,
                              void* d_out, int out_size) {
    const float* x  = (const float*)d_in[0];
    const float* w1 = (const float*)d_in[1];
    const float* b1 = (const float*)d_in[2];
    const float* w2 = (const float*)d_in[3];
    const float* b2 = (const float*)d_in[4];
    const float* w3 = (const float*)d_in[5];
    const float* b3 = (const float*)d_in[6];
    const float* wg = (const float*)d_in[7];
    float* out = (float*)d_out;

    // ~45.8 KB static smem/CTA; request max shared carveout so 3 CTAs/SM
    // aren't capped by the default split. Host-side, outside capture.
    static int carveout_set = 0;
    if (!carveout_set) {
        cudaFuncSetAttribute(tts_kernel,
                             cudaFuncAttributePreferredSharedMemoryCarveout,
                             100);
        carveout_set = 1;
    }

    dim3 grid(B_ * C_ * NTILES);   // 1792
    dim3 block(NT);                // 224
    tts_kernel<<<grid, block>>>(x, w1, b1, w2, b2, w3, b3, wg, out);
}